// round 2
// baseline (speedup 1.0000x reference)
#include <cuda_runtime.h>
#include <cstdint>

// out[n, d, b] = unique_weights[indices[n], d] * input_values[n, d, b]
// N=16384, U=1024, D=128, B=16, fp32. Pure HBM-bound streaming multiply.
//
// NOTE: JAX without x64 downcasts the "int64" indices to int32 — read as int.
// Pointers are bound by element count (all three sizes are distinct) to be
// robust to metadata ordering.

#define N_POS 16384
#define U_DIM 1024
#define D_DIM 128
#define B_DIM 16

__global__ void __launch_bounds__(256) diag_scale_kernel(
    const float* __restrict__ x,          // [N, D, B]
    const float* __restrict__ w,          // [U, D]
    const int* __restrict__ idx,          // [N] (int32)
    float* __restrict__ out)              // [N, D, B]
{
    unsigned int row = blockIdx.x * blockDim.x + threadIdx.x;  // over N*D rows
    if (row >= (unsigned int)(N_POS * D_DIM)) return;

    unsigned int n = row >> 7;            // row / 128
    unsigned int d = row & 127;           // row % 128

    unsigned int u = (unsigned int)__ldg(&idx[n]) & (U_DIM - 1);  // guard OOB
    float wv = __ldg(&w[(size_t)u * D_DIM + d]);

    const float4* __restrict__ xr = reinterpret_cast<const float4*>(x) + (size_t)row * 4;
    float4* __restrict__ orow = reinterpret_cast<float4*>(out) + (size_t)row * 4;

    // Front-batch the 4 independent float4 loads (MLP=4), then scale+store.
    float4 v0 = __ldg(&xr[0]);
    float4 v1 = __ldg(&xr[1]);
    float4 v2 = __ldg(&xr[2]);
    float4 v3 = __ldg(&xr[3]);

    v0.x *= wv; v0.y *= wv; v0.z *= wv; v0.w *= wv;
    v1.x *= wv; v1.y *= wv; v1.z *= wv; v1.w *= wv;
    v2.x *= wv; v2.y *= wv; v2.z *= wv; v2.w *= wv;
    v3.x *= wv; v3.y *= wv; v3.z *= wv; v3.w *= wv;

    orow[0] = v0;
    orow[1] = v1;
    orow[2] = v2;
    orow[3] = v3;
}

extern "C" void kernel_launch(void* const* d_in, const int* in_sizes, int n_in,
                              void* d_out, int out_size)
{
    // Bind by element count — robust to metadata ordering.
    const float* x = nullptr;    // N*D*B = 33,554,432
    const float* w = nullptr;    // U*D   = 131,072
    const int* idx = nullptr;    // N     = 16,384
    for (int i = 0; i < n_in; i++) {
        if (in_sizes[i] == N_POS * D_DIM * B_DIM)   x   = (const float*)d_in[i];
        else if (in_sizes[i] == U_DIM * D_DIM)      w   = (const float*)d_in[i];
        else if (in_sizes[i] == N_POS)              idx = (const int*)d_in[i];
    }
    float* out = (float*)d_out;

    const int rows = N_POS * D_DIM;       // 2,097,152
    const int threads = 256;
    const int blocks = (rows + threads - 1) / threads;

    diag_scale_kernel<<<blocks, threads>>>(x, w, idx, out);
}